// round 6
// baseline (speedup 1.0000x reference)
#include <cuda_runtime.h>
#include <math.h>

// Problem constants
#define Bc 32
#define Sc 1024
#define Ec 256
#define Hc 256
#define NCTA 128      // 64 CTAs per direction, 4 hidden units each
#define TPB 256       // 8 warps

// Output section offsets (floats)
#define OUT_C 16777216UL          // S*B*2H
#define OUT_S 33554432UL          // 2 * S*B*2H

// SMEM layout (float offsets)
#define OFF_WA   0        // [16 cols][772]   z-projection weights (x|h|s stacked on k)
#define OFF_WB   12352    // [8 cols][516]    r-projection weights (x|h stacked on k)
#define OFF_BA   16480    // [16]
#define OFF_BB   16496    // [16]
#define OFF_SIN  16512    // [32 b][772]      staged x(0:256) h(256:512) s(512:768)
#define OFF_PRED 41216    // [8 warps][520]   k-split partials
#define OFF_CLOC 45376    // [4 jj][32 b]     cell state (CTA-local, persistent)
#define OFF_SLOC 45504    // [8 c][32 b]      shared state (CTA-local, persistent)
#define OFF_HTMP 45760    // [4 jj][32 b]
#define OFF_MASK 45888    // [2 parity][32]
#define SMEM_FLOATS 45952
#define SMEM_BYTES (SMEM_FLOATS * 4)

// Global scratch (cross-CTA communication).
__device__ float g_h[2 * Bc * Hc];     // [dir][b][j]
__device__ float g_s[4 * Bc * Hc];     // [dir][share][b][j]
__device__ uint4 g_flags4[32];         // words: dir0 flags [0..63], dir1 flags [64..127]

__global__ void init_kernel() {
    int tid = blockIdx.x * blockDim.x + threadIdx.x;
    int stride = gridDim.x * blockDim.x;
    for (int i = tid; i < 2 * Bc * Hc; i += stride) g_h[i] = 0.0f;
    for (int i = tid; i < 4 * Bc * Hc; i += stride) g_s[i] = 0.0f;
    if (tid < 128) reinterpret_cast<unsigned*>(g_flags4)[tid] = 0u;
}

__device__ __forceinline__ float sigf(float x) { return 1.0f / (1.0f + expf(-x)); }

// Packed dual-fp32 FMA (sm_103a): d = a*b + d elementwise on 2 floats.
__device__ __forceinline__ void fma2(unsigned long long& d,
                                     const unsigned long long a,
                                     const unsigned long long b) {
    asm("fma.rn.f32x2 %0, %1, %2, %0;" : "+l"(d) : "l"(a), "l"(b));
}
__device__ __forceinline__ float pair_sum(unsigned long long v) {
    float lo = __uint_as_float((unsigned int)(v & 0xffffffffULL));
    float hi = __uint_as_float((unsigned int)(v >> 32));
    return lo + hi;
}

// cp.async helpers
__device__ __forceinline__ void cp16(const float* smem_ptr, const float* gptr) {
    unsigned sa = (unsigned)__cvta_generic_to_shared(smem_ptr);
    asm volatile("cp.async.cg.shared.global [%0], [%1], 16;" :: "r"(sa), "l"(gptr));
}
__device__ __forceinline__ void cp4(const float* smem_ptr, const float* gptr) {
    unsigned sa = (unsigned)__cvta_generic_to_shared(smem_ptr);
    asm volatile("cp.async.ca.shared.global [%0], [%1], 4;" :: "r"(sa), "l"(gptr));
}
#define CP_COMMIT asm volatile("cp.async.commit_group;")
#define CP_WAIT0  asm volatile("cp.async.wait_group 0;")
#define CP_WAIT1  asm volatile("cp.async.wait_group 1;")

// Decentralized per-direction barrier.
// arrive: one release-store of own flag (after __syncthreads).
// wait: EVERY warp polls the 64 own-direction flags (lane&15 -> one v4 each),
//       then issues its own acquire fence. No trailing __syncthreads.
__device__ __forceinline__ void barrier_arrive(int dir, int cid, unsigned e) {
    __syncthreads();   // all block work (global stores) done before release
    if (threadIdx.x == 0) {
        unsigned* f = reinterpret_cast<unsigned*>(g_flags4) + dir * 64 + cid;
        asm volatile("st.release.gpu.u32 [%0], %1;" :: "l"(f), "r"(e) : "memory");
    }
}
__device__ __forceinline__ void barrier_wait(int dir, unsigned e) {
    const int lane = threadIdx.x & 31;
    const uint4* fp = &g_flags4[dir * 16 + (lane & 15)];
    bool ok;
    do {
        uint4 v;
        asm volatile("ld.relaxed.gpu.v4.u32 {%0,%1,%2,%3}, [%4];"
                     : "=r"(v.x), "=r"(v.y), "=r"(v.z), "=r"(v.w)
                     : "l"(fp) : "memory");
        ok = (v.x >= e) && (v.y >= e) && (v.z >= e) && (v.w >= e);
    } while (!__all_sync(0xffffffffu, ok));
    asm volatile("fence.acq_rel.gpu;" ::: "memory");
}

// Accumulate one 32-k segment: NC columns, weight row stride WSTR (floats).
template<int NC, int WSTR>
__device__ __forceinline__ void accum_part(const float* __restrict__ sm,
                                           unsigned long long* acc,
                                           int in_base, int w_base) {
    const float* inb = sm + in_base;
    const float* wb  = sm + w_base;
    #pragma unroll
    for (int kb = 0; kb < 8; ++kb) {
        ulonglong2 xv = *reinterpret_cast<const ulonglong2*>(inb + kb * 4);
        #pragma unroll
        for (int c = 0; c < NC; ++c) {
            ulonglong2 wv = *reinterpret_cast<const ulonglong2*>(wb + c * WSTR + kb * 4);
            fma2(acc[c], xv.x, wv.x);
            fma2(acc[c], xv.y, wv.y);
        }
    }
}

__global__ void __launch_bounds__(TPB, 1) bislstm_kernel(
    const float* __restrict__ inputs, const float* __restrict__ mask,
    const float* __restrict__ Wx,   const float* __restrict__ Wh,
    const float* __restrict__ Ws,   const float* __restrict__ bz,
    const float* __restrict__ Wrx,  const float* __restrict__ Wrh,
    const float* __restrict__ br,
    const float* __restrict__ Wx_r, const float* __restrict__ Wh_r,
    const float* __restrict__ Ws_r, const float* __restrict__ bz_r,
    const float* __restrict__ Wrx_r,const float* __restrict__ Wrh_r,
    const float* __restrict__ br_r,
    const int* __restrict__ idx_ptr, float* __restrict__ out)
{
    extern __shared__ float sm[];
    const int tid  = threadIdx.x;
    const int warp = tid >> 5;
    const int lane = tid & 31;
    const int cta  = blockIdx.x;
    const int dir  = cta >> 6;           // 0 = fwd, 1 = rev
    const int cid  = cta & 63;
    const int jbase = cid * 4;           // this CTA's 4 hidden units
    const int idxv = *idx_ptr;
    const int w32 = warp * 32;           // warp's k-offset inside each 256-segment

    const float* pWx  = dir ? Wx_r  : Wx;
    const float* pWh  = dir ? Wh_r  : Wh;
    const float* pWs  = dir ? Ws_r  : Ws;
    const float* pB   = dir ? bz_r  : bz;
    const float* pWrx = dir ? Wrx_r : Wrx;
    const float* pWrh = dir ? Wrh_r : Wrh;
    const float* pBr  = dir ? br_r  : br;

    // ---- Load weight slices into SMEM (once) ----
    for (int i = tid; i < 16 * 768; i += TPB) {
        int k = i >> 4, c = i & 15;
        int gate = c >> 2, jj = c & 3;
        int gcol = gate * Hc + jbase + jj;
        float v;
        if (k < 256)      v = pWx[(size_t)k * (4 * Hc) + gcol];
        else if (k < 512) v = pWh[(size_t)(k - 256) * (4 * Hc) + gcol];
        else              v = pWs[(size_t)(k - 512) * (4 * Hc) + gcol];
        sm[OFF_WA + c * 772 + k] = v;
    }
    for (int i = tid; i < 8 * 512; i += TPB) {
        int k = i >> 3, c = i & 7;
        int kk = c >> 2, jj = c & 3;
        int j = jbase + jj;
        float v;
        if (k < 256) v = pWrx[(size_t)kk * Ec * Hc + (size_t)k * Hc + j];
        else         v = pWrh[(size_t)kk * Hc * Hc + (size_t)(k - 256) * Hc + j];
        sm[OFF_WB + c * 516 + k] = v;
    }
    if (tid < 16) {
        int gate = tid >> 2, jj = tid & 3;
        sm[OFF_BA + tid] = pB[gate * Hc + jbase + jj];
    }
    if (tid < 8) {
        int kk = tid >> 2, jj = tid & 3;
        sm[OFF_BB + tid] = pBr[kk * Hc + jbase + jj];
    }
    if (tid < 128) sm[OFF_CLOC + tid] = 0.0f;
    sm[OFF_SLOC + tid] = 0.0f;
    // zero h segment of SIN (step 0 sees h = 0)
    for (int i = tid; i < 32 * 256; i += TPB) {
        int b = i >> 8, r = i & 255;
        sm[OFF_SIN + b * 772 + 256 + r] = 0.0f;
    }
    // prefetch x_0 / mask_0 into parity 0 (the "x group")
    {
        const int t0 = dir ? (Sc - 1) : 0;
        for (int i = tid; i < 2048; i += TPB) {
            int b = i >> 6, k4 = i & 63;
            cp16(&sm[OFF_SIN + b * 772 + k4 * 4],
                 inputs + ((size_t)b * Sc + t0) * Ec + k4 * 4);
        }
        if (tid < 32) cp4(&sm[OFF_MASK + tid], mask + (size_t)tid * Sc + t0);
        CP_COMMIT;
    }

    unsigned e = 0;
    // acc2: z partials. Carries h-part across BAR2 (zero at step 0 since h=0).
    unsigned long long acc2[16];
    #pragma unroll
    for (int c = 0; c < 16; ++c) acc2[c] = 0ULL;
    unsigned long long accB[8];

    for (int n = 0; n < Sc; ++n) {
        const int t = dir ? (Sc - 1 - n) : n;
        const int par = n & 1;

        // ===== A: x group done; launch s stage; overlap with z x-part =====
        CP_WAIT0;     // own x/mask copies done (all groups drained)
        {
            const float* ssrc = g_s + (size_t)(dir * 2 + idxv) * (Bc * Hc);
            #pragma unroll 4
            for (int i = tid; i < 2048; i += TPB) {
                int b = i >> 6, k4 = i & 63;
                cp16(&sm[OFF_SIN + b * 772 + 512 + k4 * 4], ssrc + b * 256 + k4 * 4);
            }
            CP_COMMIT;   // s group (pending)
        }
        __syncthreads();   // everyone's x copies visible

        // z x-part (s stage in flight underneath)
        accum_part<16, 772>(sm, acc2, OFF_SIN + lane * 772 + w32, OFF_WA + w32);

        CP_WAIT0;          // own s copies done
        __syncthreads();   // everyone's s copies visible

        // z s-part + write partials
        accum_part<16, 772>(sm, acc2, OFF_SIN + lane * 772 + 512 + w32, OFF_WA + 512 + w32);
        #pragma unroll
        for (int c = 0; c < 16; ++c)
            sm[OFF_PRED + warp * 520 + c * 32 + lane] = pair_sum(acc2[c]);
        __syncthreads();

        // fused reduce + gates + mask blend
        if (tid < 128) {
            const int jj = tid >> 5, b = tid & 31;
            float zi = sm[OFF_BA + jj];
            float zf = sm[OFF_BA + 4 + jj];
            float zg = sm[OFF_BA + 8 + jj];
            float zo = sm[OFF_BA + 12 + jj];
            #pragma unroll
            for (int w = 0; w < 8; ++w) {
                const float* p = &sm[OFF_PRED + w * 520 + b];
                zi += p[(jj     ) * 32];
                zf += p[(jj +  4) * 32];
                zg += p[(jj +  8) * 32];
                zo += p[(jj + 12) * 32];
            }
            const float cold = sm[OFF_CLOC + tid];
            const float hold = sm[OFF_SIN + b * 772 + 256 + jbase + jj];
            const float m    = sm[OFF_MASK + par * 32 + b];
            const float cn = sigf(zf) * cold + sigf(zi) * tanhf(zg);
            const float hn = sigf(zo) * tanhf(cn);
            const float h = m * hn + (1.0f - m) * hold;
            const float c = m * cn + (1.0f - m) * cold;
            sm[OFF_CLOC + tid] = c;
            sm[OFF_HTMP + tid] = h;
        }
        __syncthreads();

        // publish h + h/c outputs
        if (tid < 32) {
            const int b = tid;
            float4 hv = make_float4(sm[OFF_HTMP + b],      sm[OFF_HTMP + 32 + b],
                                    sm[OFF_HTMP + 64 + b], sm[OFF_HTMP + 96 + b]);
            float4 cv = make_float4(sm[OFF_CLOC + b],      sm[OFF_CLOC + 32 + b],
                                    sm[OFF_CLOC + 64 + b], sm[OFF_CLOC + 96 + b]);
            float* hp = g_h + (size_t)dir * (Bc * Hc) + b * 256 + jbase;
            *reinterpret_cast<float4*>(hp) = hv;
            size_t ob = (size_t)t * (Bc * 512) + (size_t)b * 512 + dir * 256 + jbase;
            *reinterpret_cast<float4*>(out + ob) = hv;
            *reinterpret_cast<float4*>(out + OUT_C + ob) = cv;
        }
        barrier_arrive(dir, cid, ++e);

        // ----- BAR1 shadow: r x-part (x_n still resident) -----
        #pragma unroll
        for (int c = 0; c < 8; ++c) accB[c] = 0ULL;
        accum_part<8, 516>(sm, accB, OFF_SIN + lane * 772 + w32, OFF_WB + w32);
        barrier_wait(dir, e);

        // ===== B: launch h stage + x_{n+1} prefetch =====
        __syncthreads();   // all warps done reading x/h regions before overwrite
        {
            const float* hsrc = g_h + (size_t)dir * (Bc * Hc);
            #pragma unroll 4
            for (int i = tid; i < 2048; i += TPB) {
                int b = i >> 6, k4 = i & 63;
                cp16(&sm[OFF_SIN + b * 772 + 256 + k4 * 4], hsrc + b * 256 + k4 * 4);
            }
            CP_COMMIT;   // h group
        }
        if (n + 1 < Sc) {
            const int tn = dir ? (Sc - 2 - n) : (n + 1);
            for (int i = tid; i < 2048; i += TPB) {
                int b = i >> 6, k4 = i & 63;
                cp16(&sm[OFF_SIN + b * 772 + k4 * 4],
                     inputs + ((size_t)b * Sc + tn) * Ec + k4 * 4);
            }
            if (tid < 32)
                cp4(&sm[OFF_MASK + ((n + 1) & 1) * 32 + tid],
                    mask + (size_t)tid * Sc + tn);
        }
        CP_COMMIT;       // x group (possibly empty on last step)
        CP_WAIT1;        // h group done; x group may stay in flight
        __syncthreads(); // everyone's h copies visible

        // r h-part + partials
        accum_part<8, 516>(sm, accB, OFF_SIN + lane * 772 + 256 + w32, OFF_WB + 256 + w32);
        #pragma unroll
        for (int c = 0; c < 8; ++c)
            sm[OFF_PRED + warp * 520 + c * 32 + lane] = pair_sum(accB[c]);
        __syncthreads();

        // fused reduce + s update (256 threads)
        {
            const int o = tid;
            const int c = o >> 5, b = o & 31;
            const int jj = c & 3;
            float z = sm[OFF_BB + c];
            #pragma unroll
            for (int w = 0; w < 8; ++w) z += sm[OFF_PRED + w * 520 + o];
            const float r    = sigf(z);
            const float sold = sm[OFF_SLOC + o];
            const float cc   = sm[OFF_CLOC + jj * 32 + b];
            const float m    = sm[OFF_MASK + par * 32 + b];
            const float sn   = r * sold + (1.0f - r) * cc;
            sm[OFF_SLOC + o] = m * sn + (1.0f - m) * sold;
        }
        __syncthreads();

        // publish s + s outputs
        if (tid < 64) {
            const int kk = tid >> 5, b = tid & 31;
            const int base = (kk * 4) * 32 + b;
            float4 sv = make_float4(sm[OFF_SLOC + base],      sm[OFF_SLOC + base + 32],
                                    sm[OFF_SLOC + base + 64], sm[OFF_SLOC + base + 96]);
            *reinterpret_cast<float4*>(
                g_s + (size_t)(dir * 2 + kk) * (Bc * Hc) + b * 256 + jbase) = sv;
            size_t ob = (size_t)kk * ((size_t)Sc * Bc * 512)
                      + (size_t)t * (Bc * 512) + (size_t)b * 512 + dir * 256 + jbase;
            *reinterpret_cast<float4*>(out + OUT_S + ob) = sv;
        }
        barrier_arrive(dir, cid, ++e);

        // ----- BAR2 shadow: z h-part for step n+1 (h_n staged above) -----
        #pragma unroll
        for (int c = 0; c < 16; ++c) acc2[c] = 0ULL;
        accum_part<16, 772>(sm, acc2, OFF_SIN + lane * 772 + 256 + w32, OFF_WA + 256 + w32);
        barrier_wait(dir, e);
    }
}

extern "C" void kernel_launch(void* const* d_in, const int* in_sizes, int n_in,
                              void* d_out, int out_size) {
    (void)in_sizes; (void)n_in; (void)out_size;
    cudaFuncSetAttribute(bislstm_kernel,
                         cudaFuncAttributeMaxDynamicSharedMemorySize, SMEM_BYTES);
    init_kernel<<<64, 256>>>();
    bislstm_kernel<<<NCTA, TPB, SMEM_BYTES>>>(
        (const float*)d_in[0],  (const float*)d_in[1],
        (const float*)d_in[2],  (const float*)d_in[3],
        (const float*)d_in[4],  (const float*)d_in[5],
        (const float*)d_in[6],  (const float*)d_in[7],
        (const float*)d_in[8],
        (const float*)d_in[9],  (const float*)d_in[10],
        (const float*)d_in[11], (const float*)d_in[12],
        (const float*)d_in[13], (const float*)d_in[14],
        (const float*)d_in[15],
        (const int*)d_in[16],   (float*)d_out);
}

// round 7
// speedup vs baseline: 1.5688x; 1.5688x over previous
#include <cuda_runtime.h>
#include <math.h>

// Problem constants
#define Bc 32
#define Sc 1024
#define Ec 256
#define Hc 256
#define NCTA 128      // 64 CTAs per direction, 4 hidden units each
#define TPB 256       // 8 warps

// Output section offsets (floats)
#define OUT_C 16777216UL          // S*B*2H
#define OUT_S 33554432UL          // 2 * S*B*2H

// SMEM layout (float offsets)
#define OFF_WA   0        // [16 cols][772]   z-projection weights (x|h|s stacked on k)
#define OFF_WB   12352    // [8 cols][516]    r-projection weights (x|h stacked on k)
#define OFF_BA   16480    // [16]
#define OFF_BB   16496    // [16]
#define OFF_SIN  16512    // [32 b][772]      staged x(0:256) h(256:512) s(512:768)
#define OFF_PRED 41216    // [8 warps][520]   k-split partials
#define OFF_CLOC 45376    // [4 jj][32 b]     cell state (CTA-local, persistent)
#define OFF_SLOC 45504    // [8 c][32 b]      shared state (CTA-local, persistent)
#define OFF_HTMP 45760    // [4 jj][32 b]
#define OFF_MASK 45888    // [2 parity][32]
#define SMEM_FLOATS 45952
#define SMEM_BYTES (SMEM_FLOATS * 4)

// Global scratch (cross-CTA communication).
__device__ float g_h[2 * Bc * Hc];     // [dir][b][j]
__device__ float g_s[4 * Bc * Hc];     // [dir][share][b][j]
__device__ uint4 g_flags4[32];         // words: dir0 flags [0..63], dir1 flags [64..127]

__global__ void init_kernel() {
    int tid = blockIdx.x * blockDim.x + threadIdx.x;
    int stride = gridDim.x * blockDim.x;
    for (int i = tid; i < 2 * Bc * Hc; i += stride) g_h[i] = 0.0f;
    for (int i = tid; i < 4 * Bc * Hc; i += stride) g_s[i] = 0.0f;
    if (tid < 128) reinterpret_cast<unsigned*>(g_flags4)[tid] = 0u;
}

__device__ __forceinline__ float sigf(float x) { return 1.0f / (1.0f + expf(-x)); }

// Packed dual-fp32 FMA (sm_103a): d = a*b + d elementwise on 2 floats.
__device__ __forceinline__ void fma2(unsigned long long& d,
                                     const unsigned long long a,
                                     const unsigned long long b) {
    asm("fma.rn.f32x2 %0, %1, %2, %0;" : "+l"(d) : "l"(a), "l"(b));
}
__device__ __forceinline__ float pair_sum(unsigned long long v) {
    float lo = __uint_as_float((unsigned int)(v & 0xffffffffULL));
    float hi = __uint_as_float((unsigned int)(v >> 32));
    return lo + hi;
}

// cp.async helpers
__device__ __forceinline__ void cp16(const float* smem_ptr, const float* gptr) {
    unsigned sa = (unsigned)__cvta_generic_to_shared(smem_ptr);
    asm volatile("cp.async.cg.shared.global [%0], [%1], 16;" :: "r"(sa), "l"(gptr));
}
__device__ __forceinline__ void cp4(const float* smem_ptr, const float* gptr) {
    unsigned sa = (unsigned)__cvta_generic_to_shared(smem_ptr);
    asm volatile("cp.async.ca.shared.global [%0], [%1], 4;" :: "r"(sa), "l"(gptr));
}
#define CP_COMMIT asm volatile("cp.async.commit_group;")
#define CP_WAIT0  asm volatile("cp.async.wait_group 0;")

// Per-direction barrier. arrive: one release-store of own flag after syncthreads.
// wait: warp 0 ONLY polls the 64 own-direction flags (lane&15 -> one v4 each,
// two 128B lines per iteration), then acquire fence; others wait at syncthreads.
__device__ __forceinline__ void barrier_arrive(int dir, int cid, unsigned e) {
    __syncthreads();   // all block work (incl. global stores) issued before release
    if (threadIdx.x == 0) {
        unsigned* f = reinterpret_cast<unsigned*>(g_flags4) + dir * 64 + cid;
        asm volatile("st.release.gpu.u32 [%0], %1;" :: "l"(f), "r"(e) : "memory");
    }
}
__device__ __forceinline__ void barrier_wait(int dir, unsigned e) {
    if (threadIdx.x < 32) {
        const uint4* fp = &g_flags4[dir * 16 + (threadIdx.x & 15)];
        bool ok;
        do {
            uint4 v;
            asm volatile("ld.relaxed.gpu.v4.u32 {%0,%1,%2,%3}, [%4];"
                         : "=r"(v.x), "=r"(v.y), "=r"(v.z), "=r"(v.w)
                         : "l"(fp) : "memory");
            ok = (v.x >= e) && (v.y >= e) && (v.z >= e) && (v.w >= e);
        } while (!__all_sync(0xffffffffu, ok));
        asm volatile("fence.acq_rel.gpu;" ::: "memory");
    }
    __syncthreads();
}

// Accumulate one 32-k segment: NC columns, weight row stride WSTR (floats).
template<int NC, int WSTR>
__device__ __forceinline__ void accum_part(const float* __restrict__ sm,
                                           unsigned long long* acc,
                                           int in_base, int w_base) {
    const float* inb = sm + in_base;
    const float* wb  = sm + w_base;
    #pragma unroll
    for (int kb = 0; kb < 8; ++kb) {
        ulonglong2 xv = *reinterpret_cast<const ulonglong2*>(inb + kb * 4);
        #pragma unroll
        for (int c = 0; c < NC; ++c) {
            ulonglong2 wv = *reinterpret_cast<const ulonglong2*>(wb + c * WSTR + kb * 4);
            fma2(acc[c], xv.x, wv.x);
            fma2(acc[c], xv.y, wv.y);
        }
    }
}

__global__ void __launch_bounds__(TPB, 1) bislstm_kernel(
    const float* __restrict__ inputs, const float* __restrict__ mask,
    const float* __restrict__ Wx,   const float* __restrict__ Wh,
    const float* __restrict__ Ws,   const float* __restrict__ bz,
    const float* __restrict__ Wrx,  const float* __restrict__ Wrh,
    const float* __restrict__ br,
    const float* __restrict__ Wx_r, const float* __restrict__ Wh_r,
    const float* __restrict__ Ws_r, const float* __restrict__ bz_r,
    const float* __restrict__ Wrx_r,const float* __restrict__ Wrh_r,
    const float* __restrict__ br_r,
    const int* __restrict__ idx_ptr, float* __restrict__ out)
{
    extern __shared__ float sm[];
    const int tid  = threadIdx.x;
    const int warp = tid >> 5;
    const int lane = tid & 31;
    const int cta  = blockIdx.x;
    const int dir  = cta >> 6;           // 0 = fwd, 1 = rev
    const int cid  = cta & 63;
    const int jbase = cid * 4;           // this CTA's 4 hidden units
    const int idxv = *idx_ptr;
    const int w32 = warp * 32;           // warp's k-offset inside each 256-segment

    const float* pWx  = dir ? Wx_r  : Wx;
    const float* pWh  = dir ? Wh_r  : Wh;
    const float* pWs  = dir ? Ws_r  : Ws;
    const float* pB   = dir ? bz_r  : bz;
    const float* pWrx = dir ? Wrx_r : Wrx;
    const float* pWrh = dir ? Wrh_r : Wrh;
    const float* pBr  = dir ? br_r  : br;

    // ---- Load weight slices into SMEM (once) ----
    for (int i = tid; i < 16 * 768; i += TPB) {
        int k = i >> 4, c = i & 15;
        int gate = c >> 2, jj = c & 3;
        int gcol = gate * Hc + jbase + jj;
        float v;
        if (k < 256)      v = pWx[(size_t)k * (4 * Hc) + gcol];
        else if (k < 512) v = pWh[(size_t)(k - 256) * (4 * Hc) + gcol];
        else              v = pWs[(size_t)(k - 512) * (4 * Hc) + gcol];
        sm[OFF_WA + c * 772 + k] = v;
    }
    for (int i = tid; i < 8 * 512; i += TPB) {
        int k = i >> 3, c = i & 7;
        int kk = c >> 2, jj = c & 3;
        int j = jbase + jj;
        float v;
        if (k < 256) v = pWrx[(size_t)kk * Ec * Hc + (size_t)k * Hc + j];
        else         v = pWrh[(size_t)kk * Hc * Hc + (size_t)(k - 256) * Hc + j];
        sm[OFF_WB + c * 516 + k] = v;
    }
    if (tid < 16) {
        int gate = tid >> 2, jj = tid & 3;
        sm[OFF_BA + tid] = pB[gate * Hc + jbase + jj];
    }
    if (tid < 8) {
        int kk = tid >> 2, jj = tid & 3;
        sm[OFF_BB + tid] = pBr[kk * Hc + jbase + jj];
    }
    if (tid < 128) sm[OFF_CLOC + tid] = 0.0f;
    sm[OFF_SLOC + tid] = 0.0f;
    // zero h segment of SIN (step 0 sees h = 0)
    for (int i = tid; i < 32 * 256; i += TPB) {
        int b = i >> 8, r = i & 255;
        sm[OFF_SIN + b * 772 + 256 + r] = 0.0f;
    }
    // prefetch x_0 / mask_0 (parity 0), make visible
    {
        const int t0 = dir ? (Sc - 1) : 0;
        for (int i = tid; i < 2048; i += TPB) {
            int b = i >> 6, k4 = i & 63;
            cp16(&sm[OFF_SIN + b * 772 + k4 * 4],
                 inputs + ((size_t)b * Sc + t0) * Ec + k4 * 4);
        }
        if (tid < 32) cp4(&sm[OFF_MASK + tid], mask + (size_t)tid * Sc + t0);
        CP_COMMIT; CP_WAIT0;
    }
    __syncthreads();

    unsigned e = 0;
    // acc2: z partials. Carries h-part across BAR2 (zero at step 0 since h=0).
    unsigned long long acc2[16];
    #pragma unroll
    for (int c = 0; c < 16; ++c) acc2[c] = 0ULL;
    unsigned long long accB[8];

    for (int n = 0; n < Sc; ++n) {
        const int t = dir ? (Sc - 1 - n) : n;
        const int par = n & 1;

        // ===== A1: s reg-load (L2) overlapped with z x-part =====
        float4 sreg[8];
        {
            const float* ssrc = g_s + (size_t)(dir * 2 + idxv) * (Bc * Hc);
            #pragma unroll
            for (int it = 0; it < 8; ++it) {
                int i = tid + it * TPB; int b = i >> 6, k4 = i & 63;
                sreg[it] = __ldcg(reinterpret_cast<const float4*>(ssrc + b * 256 + k4 * 4));
            }
        }
        accum_part<16, 772>(sm, acc2, OFF_SIN + lane * 772 + w32, OFF_WA + w32);
        #pragma unroll
        for (int it = 0; it < 8; ++it) {
            int i = tid + it * TPB; int b = i >> 6, k4 = i & 63;
            *reinterpret_cast<float4*>(&sm[OFF_SIN + b * 772 + 512 + k4 * 4]) = sreg[it];
        }
        __syncthreads();

        // ===== A2: z s-part + partials =====
        accum_part<16, 772>(sm, acc2, OFF_SIN + lane * 772 + 512 + w32, OFF_WA + 512 + w32);
        #pragma unroll
        for (int c = 0; c < 16; ++c)
            sm[OFF_PRED + warp * 520 + c * 32 + lane] = pair_sum(acc2[c]);
        __syncthreads();

        // ===== A3: fused reduce + gates + mask blend =====
        if (tid < 128) {
            const int jj = tid >> 5, b = tid & 31;
            float zi = sm[OFF_BA + jj];
            float zf = sm[OFF_BA + 4 + jj];
            float zg = sm[OFF_BA + 8 + jj];
            float zo = sm[OFF_BA + 12 + jj];
            #pragma unroll
            for (int w = 0; w < 8; ++w) {
                const float* p = &sm[OFF_PRED + w * 520 + b];
                zi += p[(jj     ) * 32];
                zf += p[(jj +  4) * 32];
                zg += p[(jj +  8) * 32];
                zo += p[(jj + 12) * 32];
            }
            const float cold = sm[OFF_CLOC + tid];
            const float hold = sm[OFF_SIN + b * 772 + 256 + jbase + jj];
            const float m    = sm[OFF_MASK + par * 32 + b];
            const float cn = sigf(zf) * cold + sigf(zi) * tanhf(zg);
            const float hn = sigf(zo) * tanhf(cn);
            const float h = m * hn + (1.0f - m) * hold;
            const float c = m * cn + (1.0f - m) * cold;
            sm[OFF_CLOC + tid] = c;
            sm[OFF_HTMP + tid] = h;
        }
        __syncthreads();

        // ===== A4: publish h + h/c outputs =====
        if (tid < 32) {
            const int b = tid;
            float4 hv = make_float4(sm[OFF_HTMP + b],      sm[OFF_HTMP + 32 + b],
                                    sm[OFF_HTMP + 64 + b], sm[OFF_HTMP + 96 + b]);
            float4 cv = make_float4(sm[OFF_CLOC + b],      sm[OFF_CLOC + 32 + b],
                                    sm[OFF_CLOC + 64 + b], sm[OFF_CLOC + 96 + b]);
            float* hp = g_h + (size_t)dir * (Bc * Hc) + b * 256 + jbase;
            *reinterpret_cast<float4*>(hp) = hv;
            size_t ob = (size_t)t * (Bc * 512) + (size_t)b * 512 + dir * 256 + jbase;
            *reinterpret_cast<float4*>(out + ob) = hv;
            *reinterpret_cast<float4*>(out + OUT_C + ob) = cv;
        }
        barrier_arrive(dir, cid, ++e);
        barrier_wait(dir, e);          // empty shadow: poll starts immediately

        // ===== B1: h reg-load (L2) overlapped with r x-part =====
        float4 hreg[8];
        {
            const float* hsrc = g_h + (size_t)dir * (Bc * Hc);
            #pragma unroll
            for (int it = 0; it < 8; ++it) {
                int i = tid + it * TPB; int b = i >> 6, k4 = i & 63;
                hreg[it] = __ldcg(reinterpret_cast<const float4*>(hsrc + b * 256 + k4 * 4));
            }
        }
        #pragma unroll
        for (int c = 0; c < 8; ++c) accB[c] = 0ULL;
        accum_part<8, 516>(sm, accB, OFF_SIN + lane * 772 + w32, OFF_WB + w32);
        #pragma unroll
        for (int it = 0; it < 8; ++it) {
            int i = tid + it * TPB; int b = i >> 6, k4 = i & 63;
            *reinterpret_cast<float4*>(&sm[OFF_SIN + b * 772 + 256 + k4 * 4]) = hreg[it];
        }
        __syncthreads();   // h visible; x reads (r x-part) done everywhere

        // issue x_{n+1}/mask prefetch (lands during BAR2 shadow / next A)
        if (n + 1 < Sc) {
            const int tn = dir ? (Sc - 2 - n) : (n + 1);
            for (int i = tid; i < 2048; i += TPB) {
                int b = i >> 6, k4 = i & 63;
                cp16(&sm[OFF_SIN + b * 772 + k4 * 4],
                     inputs + ((size_t)b * Sc + tn) * Ec + k4 * 4);
            }
            if (tid < 32)
                cp4(&sm[OFF_MASK + ((n + 1) & 1) * 32 + tid],
                    mask + (size_t)tid * Sc + tn);
        }
        CP_COMMIT;

        // ===== B2: r h-part + partials =====
        accum_part<8, 516>(sm, accB, OFF_SIN + lane * 772 + 256 + w32, OFF_WB + 256 + w32);
        #pragma unroll
        for (int c = 0; c < 8; ++c)
            sm[OFF_PRED + warp * 520 + c * 32 + lane] = pair_sum(accB[c]);
        __syncthreads();

        // ===== B3: fused reduce + s update (256 threads) =====
        {
            const int o = tid;
            const int c = o >> 5, b = o & 31;
            const int jj = c & 3;
            float z = sm[OFF_BB + c];
            #pragma unroll
            for (int w = 0; w < 8; ++w) z += sm[OFF_PRED + w * 520 + o];
            const float r    = sigf(z);
            const float sold = sm[OFF_SLOC + o];
            const float cc   = sm[OFF_CLOC + jj * 32 + b];
            const float m    = sm[OFF_MASK + par * 32 + b];
            const float sn   = r * sold + (1.0f - r) * cc;
            sm[OFF_SLOC + o] = m * sn + (1.0f - m) * sold;
        }
        __syncthreads();

        // ===== B4: publish s + s outputs =====
        if (tid < 64) {
            const int kk = tid >> 5, b = tid & 31;
            const int base = (kk * 4) * 32 + b;
            float4 sv = make_float4(sm[OFF_SLOC + base],      sm[OFF_SLOC + base + 32],
                                    sm[OFF_SLOC + base + 64], sm[OFF_SLOC + base + 96]);
            *reinterpret_cast<float4*>(
                g_s + (size_t)(dir * 2 + kk) * (Bc * Hc) + b * 256 + jbase) = sv;
            size_t ob = (size_t)kk * ((size_t)Sc * Bc * 512)
                      + (size_t)t * (Bc * 512) + (size_t)b * 512 + dir * 256 + jbase;
            *reinterpret_cast<float4*>(out + OUT_S + ob) = sv;
        }
        barrier_arrive(dir, cid, ++e);

        // ----- BAR2 shadow: z h-part for step n+1 (h_n staged in B1) -----
        #pragma unroll
        for (int c = 0; c < 16; ++c) acc2[c] = 0ULL;
        accum_part<16, 772>(sm, acc2, OFF_SIN + lane * 772 + 256 + w32, OFF_WA + 256 + w32);
        CP_WAIT0;            // x_{n+1} copies done (own); wait's sync makes visible
        barrier_wait(dir, e);
    }
}

extern "C" void kernel_launch(void* const* d_in, const int* in_sizes, int n_in,
                              void* d_out, int out_size) {
    (void)in_sizes; (void)n_in; (void)out_size;
    cudaFuncSetAttribute(bislstm_kernel,
                         cudaFuncAttributeMaxDynamicSharedMemorySize, SMEM_BYTES);
    init_kernel<<<64, 256>>>();
    bislstm_kernel<<<NCTA, TPB, SMEM_BYTES>>>(
        (const float*)d_in[0],  (const float*)d_in[1],
        (const float*)d_in[2],  (const float*)d_in[3],
        (const float*)d_in[4],  (const float*)d_in[5],
        (const float*)d_in[6],  (const float*)d_in[7],
        (const float*)d_in[8],
        (const float*)d_in[9],  (const float*)d_in[10],
        (const float*)d_in[11], (const float*)d_in[12],
        (const float*)d_in[13], (const float*)d_in[14],
        (const float*)d_in[15],
        (const int*)d_in[16],   (float*)d_out);
}

// round 8
// speedup vs baseline: 1.9989x; 1.2742x over previous
#include <cuda_runtime.h>
#include <math.h>

// Problem constants
#define Bc 32
#define Sc 1024
#define Ec 256
#define Hc 256
#define NCTA 128      // 64 CTAs per direction, 4 hidden units each
#define TPB 256       // 8 warps

// Output section offsets (floats)
#define OUT_C 16777216UL          // S*B*2H
#define OUT_S 33554432UL          // 2 * S*B*2H

// SMEM layout (float offsets)
#define OFF_WA   0        // [16 cols][772]   z-projection weights (x|h|s stacked on k)
#define OFF_WB   12352    // [8 cols][516]    r-projection weights (x|h stacked on k)
#define OFF_BA   16480    // [16]
#define OFF_BB   16496    // [16]
#define OFF_SIN  16512    // [32 b][772]      staged x only (0:256); h/s fed via regs
#define OFF_PRED 41216    // [8 warps][520]   k-split partials
#define OFF_CLOC 45376    // [4 jj][32 b]     cell state (CTA-local, persistent)
#define OFF_SLOC 45504    // [8 c][32 b]      shared state (CTA-local, persistent)
#define OFF_HTMP 45760    // [4 jj][32 b]     h state (CTA-local, persistent)
#define OFF_MASK 45888    // [32]
#define SMEM_FLOATS 45920
#define SMEM_BYTES (SMEM_FLOATS * 4)

// Global scratch (cross-CTA communication).
__device__ float g_h[2 * Bc * Hc];     // [dir][b][j]
__device__ float g_s[4 * Bc * Hc];     // [dir][share][b][j]
__device__ uint4 g_flags4[32];         // 128 packed epoch flags (512B)

__global__ void init_kernel() {
    int tid = blockIdx.x * blockDim.x + threadIdx.x;
    int stride = gridDim.x * blockDim.x;
    for (int i = tid; i < 2 * Bc * Hc; i += stride) g_h[i] = 0.0f;
    for (int i = tid; i < 4 * Bc * Hc; i += stride) g_s[i] = 0.0f;
    if (tid < 128) reinterpret_cast<unsigned*>(g_flags4)[tid] = 0u;
}

__device__ __forceinline__ float sigf(float x) { return 1.0f / (1.0f + expf(-x)); }

// Packed dual-fp32 FMA (sm_103a): d = a*b + d elementwise on 2 floats.
__device__ __forceinline__ void fma2(unsigned long long& d,
                                     const unsigned long long a,
                                     const unsigned long long b) {
    asm("fma.rn.f32x2 %0, %1, %2, %0;" : "+l"(d) : "l"(a), "l"(b));
}
__device__ __forceinline__ float pair_sum(unsigned long long v) {
    float lo = __uint_as_float((unsigned int)(v & 0xffffffffULL));
    float hi = __uint_as_float((unsigned int)(v >> 32));
    return lo + hi;
}

// cp.async helpers
__device__ __forceinline__ void cp16(const float* smem_ptr, const float* gptr) {
    unsigned sa = (unsigned)__cvta_generic_to_shared(smem_ptr);
    asm volatile("cp.async.cg.shared.global [%0], [%1], 16;" :: "r"(sa), "l"(gptr));
}
__device__ __forceinline__ void cp4(const float* smem_ptr, const float* gptr) {
    unsigned sa = (unsigned)__cvta_generic_to_shared(smem_ptr);
    asm volatile("cp.async.ca.shared.global [%0], [%1], 4;" :: "r"(sa), "l"(gptr));
}
#define CP_COMMIT asm volatile("cp.async.commit_group;")
#define CP_WAIT0  asm volatile("cp.async.wait_group 0;")

// Decentralized barrier (identical to R4): arrive = release own flag after
// syncthreads; wait = warp0 polls all 128 flags (one v4 per lane), acquire
// fence, then block-wide release via syncthreads.
__device__ __forceinline__ void barrier_arrive(int cta, unsigned e) {
    __syncthreads();   // all block work (global stores) issued before release
    if (threadIdx.x == 0) {
        unsigned* f = reinterpret_cast<unsigned*>(g_flags4) + cta;
        asm volatile("st.release.gpu.u32 [%0], %1;" :: "l"(f), "r"(e) : "memory");
    }
}
__device__ __forceinline__ void barrier_wait(unsigned e) {
    if (threadIdx.x < 32) {
        const uint4* fp = &g_flags4[threadIdx.x];
        bool ok;
        do {
            uint4 v;
            asm volatile("ld.relaxed.gpu.v4.u32 {%0,%1,%2,%3}, [%4];"
                         : "=r"(v.x), "=r"(v.y), "=r"(v.z), "=r"(v.w)
                         : "l"(fp) : "memory");
            ok = (v.x >= e) && (v.y >= e) && (v.z >= e) && (v.w >= e);
        } while (!__all_sync(0xffffffffu, ok));
        asm volatile("fence.acq_rel.gpu;" ::: "memory");
    }
    __syncthreads();
}

// Accumulate one 32-k segment with SMEM input (x): NC cols, stride WSTR.
template<int NC, int WSTR>
__device__ __forceinline__ void accum_part(const float* __restrict__ sm,
                                           unsigned long long* acc,
                                           int in_base, int w_base) {
    const float* inb = sm + in_base;
    const float* wb  = sm + w_base;
    #pragma unroll
    for (int kb = 0; kb < 8; ++kb) {
        ulonglong2 xv = *reinterpret_cast<const ulonglong2*>(inb + kb * 4);
        #pragma unroll
        for (int c = 0; c < NC; ++c) {
            ulonglong2 wv = *reinterpret_cast<const ulonglong2*>(wb + c * WSTR + kb * 4);
            fma2(acc[c], xv.x, wv.x);
            fma2(acc[c], xv.y, wv.y);
        }
    }
}

// Accumulate one 32-k segment with REGISTER input (s/h slices).
template<int NC, int WSTR>
__device__ __forceinline__ void accum_reg(const float* __restrict__ sm,
                                          unsigned long long* acc,
                                          const ulonglong2* __restrict__ xr,
                                          int w_base) {
    const float* wb = sm + w_base;
    #pragma unroll
    for (int kb = 0; kb < 8; ++kb) {
        #pragma unroll
        for (int c = 0; c < NC; ++c) {
            ulonglong2 wv = *reinterpret_cast<const ulonglong2*>(wb + c * WSTR + kb * 4);
            fma2(acc[c], xr[kb].x, wv.x);
            fma2(acc[c], xr[kb].y, wv.y);
        }
    }
}

__global__ void __launch_bounds__(TPB, 1) bislstm_kernel(
    const float* __restrict__ inputs, const float* __restrict__ mask,
    const float* __restrict__ Wx,   const float* __restrict__ Wh,
    const float* __restrict__ Ws,   const float* __restrict__ bz,
    const float* __restrict__ Wrx,  const float* __restrict__ Wrh,
    const float* __restrict__ br,
    const float* __restrict__ Wx_r, const float* __restrict__ Wh_r,
    const float* __restrict__ Ws_r, const float* __restrict__ bz_r,
    const float* __restrict__ Wrx_r,const float* __restrict__ Wrh_r,
    const float* __restrict__ br_r,
    const int* __restrict__ idx_ptr, float* __restrict__ out)
{
    extern __shared__ float sm[];
    const int tid  = threadIdx.x;
    const int warp = tid >> 5;
    const int lane = tid & 31;
    const int cta  = blockIdx.x;
    const int dir  = cta >> 6;           // 0 = fwd, 1 = rev
    const int cid  = cta & 63;
    const int jbase = cid * 4;           // this CTA's 4 hidden units
    const int idxv = *idx_ptr;
    const int w32 = warp * 32;           // warp's k-offset inside each 256-segment

    const float* pWx  = dir ? Wx_r  : Wx;
    const float* pWh  = dir ? Wh_r  : Wh;
    const float* pWs  = dir ? Ws_r  : Ws;
    const float* pB   = dir ? bz_r  : bz;
    const float* pWrx = dir ? Wrx_r : Wrx;
    const float* pWrh = dir ? Wrh_r : Wrh;
    const float* pBr  = dir ? br_r  : br;

    // ---- Load weight slices into SMEM (once) ----
    for (int i = tid; i < 16 * 768; i += TPB) {
        int k = i >> 4, c = i & 15;
        int gate = c >> 2, jj = c & 3;
        int gcol = gate * Hc + jbase + jj;
        float v;
        if (k < 256)      v = pWx[(size_t)k * (4 * Hc) + gcol];
        else if (k < 512) v = pWh[(size_t)(k - 256) * (4 * Hc) + gcol];
        else              v = pWs[(size_t)(k - 512) * (4 * Hc) + gcol];
        sm[OFF_WA + c * 772 + k] = v;
    }
    for (int i = tid; i < 8 * 512; i += TPB) {
        int k = i >> 3, c = i & 7;
        int kk = c >> 2, jj = c & 3;
        int j = jbase + jj;
        float v;
        if (k < 256) v = pWrx[(size_t)kk * Ec * Hc + (size_t)k * Hc + j];
        else         v = pWrh[(size_t)kk * Hc * Hc + (size_t)(k - 256) * Hc + j];
        sm[OFF_WB + c * 516 + k] = v;
    }
    if (tid < 16) {
        int gate = tid >> 2, jj = tid & 3;
        sm[OFF_BA + tid] = pB[gate * Hc + jbase + jj];
    }
    if (tid < 8) {
        int kk = tid >> 2, jj = tid & 3;
        sm[OFF_BB + tid] = pBr[kk * Hc + jbase + jj];
    }
    if (tid < 128) { sm[OFF_CLOC + tid] = 0.0f; sm[OFF_HTMP + tid] = 0.0f; }
    sm[OFF_SLOC + tid] = 0.0f;
    // prefetch x_0 and mask_0
    {
        const int t0 = dir ? (Sc - 1) : 0;
        for (int i = tid; i < 2048; i += TPB) {
            int b = i >> 6, k4 = i & 63;
            cp16(&sm[OFF_SIN + b * 772 + k4 * 4],
                 inputs + ((size_t)b * Sc + t0) * Ec + k4 * 4);
        }
        if (tid < 32) cp4(&sm[OFF_MASK + tid], mask + (size_t)tid * Sc + t0);
        CP_COMMIT;
    }

    unsigned e = 0;
    // acc2: z partials. Carries h-part across BAR2 (zero at step 0 since h=0).
    unsigned long long acc2[16];
    #pragma unroll
    for (int c = 0; c < 16; ++c) acc2[c] = 0ULL;
    unsigned long long accB[8];
    ulonglong2 hreg[8];

    // Per-lane global slice pointers: lane handles batch b=lane, k-slice w32.
    const float* ssrc = g_s + (size_t)(dir * 2 + idxv) * (Bc * Hc) + lane * 256 + w32;
    const float* hsrc = g_h + (size_t)dir * (Bc * Hc) + lane * 256 + w32;

    for (int n = 0; n < Sc; ++n) {
        const int t = dir ? (Sc - 1 - n) : n;

        // ===== A1: issue s reg-loads (L2), wait x, compute z x-part under them =====
        ulonglong2 sreg[8];
        #pragma unroll
        for (int j = 0; j < 8; ++j)
            sreg[j] = __ldcg(reinterpret_cast<const ulonglong2*>(ssrc + j * 4));
        CP_WAIT0;          // own x/mask copies done
        __syncthreads();   // everyone's x copies visible
        accum_part<16, 772>(sm, acc2, OFF_SIN + lane * 772 + w32, OFF_WA + w32);

        // ===== A2: z s-part (registers) + partials =====
        accum_reg<16, 772>(sm, acc2, sreg, OFF_WA + 512 + w32);
        #pragma unroll
        for (int c = 0; c < 16; ++c)
            sm[OFF_PRED + warp * 520 + c * 32 + lane] = pair_sum(acc2[c]);
        __syncthreads();

        // ===== A3: fused reduce + gates + mask blend =====
        if (tid < 128) {
            const int jj = tid >> 5, b = tid & 31;
            float zi = sm[OFF_BA + jj];
            float zf = sm[OFF_BA + 4 + jj];
            float zg = sm[OFF_BA + 8 + jj];
            float zo = sm[OFF_BA + 12 + jj];
            #pragma unroll
            for (int w = 0; w < 8; ++w) {
                const float* p = &sm[OFF_PRED + w * 520 + b];
                zi += p[(jj     ) * 32];
                zf += p[(jj +  4) * 32];
                zg += p[(jj +  8) * 32];
                zo += p[(jj + 12) * 32];
            }
            const float cold = sm[OFF_CLOC + tid];
            const float hold = sm[OFF_HTMP + tid];   // previous step's local h
            const float m    = sm[OFF_MASK + b];
            const float cn = sigf(zf) * cold + sigf(zi) * tanhf(zg);
            const float hn = sigf(zo) * tanhf(cn);
            const float h = m * hn + (1.0f - m) * hold;
            const float c = m * cn + (1.0f - m) * cold;
            sm[OFF_CLOC + tid] = c;
            sm[OFF_HTMP + tid] = h;
        }
        __syncthreads();

        // ===== A4: publish h + h/c outputs =====
        if (tid < 32) {
            const int b = tid;
            float4 hv = make_float4(sm[OFF_HTMP + b],      sm[OFF_HTMP + 32 + b],
                                    sm[OFF_HTMP + 64 + b], sm[OFF_HTMP + 96 + b]);
            float4 cv = make_float4(sm[OFF_CLOC + b],      sm[OFF_CLOC + 32 + b],
                                    sm[OFF_CLOC + 64 + b], sm[OFF_CLOC + 96 + b]);
            float* hp = g_h + (size_t)dir * (Bc * Hc) + b * 256 + jbase;
            *reinterpret_cast<float4*>(hp) = hv;
            size_t ob = (size_t)t * (Bc * 512) + (size_t)b * 512 + dir * 256 + jbase;
            *reinterpret_cast<float4*>(out + ob) = hv;
            *reinterpret_cast<float4*>(out + OUT_C + ob) = cv;
        }
        barrier_arrive(cta, ++e);

        // ----- BAR1 shadow: r x-part (x_n still resident in SIN) -----
        #pragma unroll
        for (int c = 0; c < 8; ++c) accB[c] = 0ULL;
        accum_part<8, 516>(sm, accB, OFF_SIN + lane * 772 + w32, OFF_WB + w32);
        barrier_wait(e);

        // ===== B1: h reg-loads (L2) feeding r h-part directly =====
        #pragma unroll
        for (int j = 0; j < 8; ++j)
            hreg[j] = __ldcg(reinterpret_cast<const ulonglong2*>(hsrc + j * 4));
        accum_reg<8, 516>(sm, accB, hreg, OFF_WB + 256 + w32);
        #pragma unroll
        for (int c = 0; c < 8; ++c)
            sm[OFF_PRED + warp * 520 + c * 32 + lane] = pair_sum(accB[c]);
        __syncthreads();

        // ===== B2: fused reduce + s update (256 threads) =====
        {
            const int o = tid;
            const int c = o >> 5, b = o & 31;
            const int jj = c & 3;
            float z = sm[OFF_BB + c];
            #pragma unroll
            for (int w = 0; w < 8; ++w) z += sm[OFF_PRED + w * 520 + o];
            const float r    = sigf(z);
            const float sold = sm[OFF_SLOC + o];
            const float cc   = sm[OFF_CLOC + jj * 32 + b];
            const float m    = sm[OFF_MASK + b];
            const float sn   = r * sold + (1.0f - r) * cc;
            sm[OFF_SLOC + o] = m * sn + (1.0f - m) * sold;
        }
        __syncthreads();

        // ===== B3: publish s + s outputs; prefetch x_{n+1}/mask =====
        if (tid < 64) {
            const int kk = tid >> 5, b = tid & 31;
            const int base = (kk * 4) * 32 + b;
            float4 sv = make_float4(sm[OFF_SLOC + base],      sm[OFF_SLOC + base + 32],
                                    sm[OFF_SLOC + base + 64], sm[OFF_SLOC + base + 96]);
            *reinterpret_cast<float4*>(
                g_s + (size_t)(dir * 2 + kk) * (Bc * Hc) + b * 256 + jbase) = sv;
            size_t ob = (size_t)kk * ((size_t)Sc * Bc * 512)
                      + (size_t)t * (Bc * 512) + (size_t)b * 512 + dir * 256 + jbase;
            *reinterpret_cast<float4*>(out + OUT_S + ob) = sv;
        }
        if (n + 1 < Sc) {
            const int tn = dir ? (Sc - 2 - n) : (n + 1);
            for (int i = tid; i < 2048; i += TPB) {
                int b = i >> 6, k4 = i & 63;
                cp16(&sm[OFF_SIN + b * 772 + k4 * 4],
                     inputs + ((size_t)b * Sc + tn) * Ec + k4 * 4);
            }
            if (tid < 32) cp4(&sm[OFF_MASK + tid], mask + (size_t)tid * Sc + tn);
            CP_COMMIT;
        }
        barrier_arrive(cta, ++e);

        // ----- BAR2 shadow: z h-part for step n+1 (from hreg, no loads) -----
        #pragma unroll
        for (int c = 0; c < 16; ++c) acc2[c] = 0ULL;
        accum_reg<16, 772>(sm, acc2, hreg, OFF_WA + 256 + w32);
        barrier_wait(e);
    }
}

extern "C" void kernel_launch(void* const* d_in, const int* in_sizes, int n_in,
                              void* d_out, int out_size) {
    (void)in_sizes; (void)n_in; (void)out_size;
    cudaFuncSetAttribute(bislstm_kernel,
                         cudaFuncAttributeMaxDynamicSharedMemorySize, SMEM_BYTES);
    init_kernel<<<64, 256>>>();
    bislstm_kernel<<<NCTA, TPB, SMEM_BYTES>>>(
        (const float*)d_in[0],  (const float*)d_in[1],
        (const float*)d_in[2],  (const float*)d_in[3],
        (const float*)d_in[4],  (const float*)d_in[5],
        (const float*)d_in[6],  (const float*)d_in[7],
        (const float*)d_in[8],
        (const float*)d_in[9],  (const float*)d_in[10],
        (const float*)d_in[11], (const float*)d_in[12],
        (const float*)d_in[13], (const float*)d_in[14],
        (const float*)d_in[15],
        (const int*)d_in[16],   (float*)d_out);
}

// round 9
// speedup vs baseline: 2.1107x; 1.0559x over previous
#include <cuda_runtime.h>
#include <math.h>

// Problem constants
#define Bc 32
#define Sc 1024
#define Ec 256
#define Hc 256
#define NCTA 128      // 64 CTAs per direction, 4 hidden units each
#define TPB 256       // 8 warps

// Output section offsets (floats)
#define OUT_C 16777216UL          // S*B*2H
#define OUT_S 33554432UL          // 2 * S*B*2H

// SMEM layout (float offsets)
#define OFF_WA   0        // [16 cols][772]   z-projection weights (x|h|s stacked on k)
#define OFF_WB   12352    // [8 cols][516]    r-projection weights (x|h stacked on k)
#define OFF_BA   16480    // [16]
#define OFF_BB   16496    // [16]
#define OFF_SIN  16512    // [32 b][772]      staged x only (0:256); h/s fed via regs
#define OFF_PRED 41216    // [8 warps][520]   k-split partials
#define OFF_CLOC 45376    // [4 jj][32 b]     cell state (CTA-local, persistent)
#define OFF_SLOC 45504    // [8 c][32 b]      shared state (CTA-local, persistent)
#define OFF_HTMP 45760    // [4 jj][32 b]     h state (CTA-local, persistent)
#define OFF_MASK 45888    // [32]
#define SMEM_FLOATS 45920
#define SMEM_BYTES (SMEM_FLOATS * 4)

// Global scratch (cross-CTA communication).
__device__ float g_h[2 * Bc * Hc];     // [dir][b][j]
__device__ float g_s[4 * Bc * Hc];     // [dir][share][b][j]
__device__ uint4 g_flags4[32];         // 128 packed epoch flags (512B)

__global__ void init_kernel() {
    int tid = blockIdx.x * blockDim.x + threadIdx.x;
    int stride = gridDim.x * blockDim.x;
    for (int i = tid; i < 2 * Bc * Hc; i += stride) g_h[i] = 0.0f;
    for (int i = tid; i < 4 * Bc * Hc; i += stride) g_s[i] = 0.0f;
    if (tid < 128) reinterpret_cast<unsigned*>(g_flags4)[tid] = 0u;
}

// Fast MUFU-based sigmoid / tanh (ex2.approx + rcp.approx; err ~1e-6,
// correct saturation at +/-inf). NOT tanh.approx (6e-4 err, too coarse
// for a 1024-step recurrence).
__device__ __forceinline__ float sigf(float x) {
    return __fdividef(1.0f, 1.0f + __expf(-x));
}
__device__ __forceinline__ float tanhf_fast(float x) {
    return 1.0f - __fdividef(2.0f, __expf(2.0f * x) + 1.0f);
}

// Packed dual-fp32 FMA (sm_103a): d = a*b + d elementwise on 2 floats.
__device__ __forceinline__ void fma2(unsigned long long& d,
                                     const unsigned long long a,
                                     const unsigned long long b) {
    asm("fma.rn.f32x2 %0, %1, %2, %0;" : "+l"(d) : "l"(a), "l"(b));
}
__device__ __forceinline__ float pair_sum(unsigned long long v) {
    float lo = __uint_as_float((unsigned int)(v & 0xffffffffULL));
    float hi = __uint_as_float((unsigned int)(v >> 32));
    return lo + hi;
}

// cp.async helpers
__device__ __forceinline__ void cp16(const float* smem_ptr, const float* gptr) {
    unsigned sa = (unsigned)__cvta_generic_to_shared(smem_ptr);
    asm volatile("cp.async.cg.shared.global [%0], [%1], 16;" :: "r"(sa), "l"(gptr));
}
__device__ __forceinline__ void cp4(const float* smem_ptr, const float* gptr) {
    unsigned sa = (unsigned)__cvta_generic_to_shared(smem_ptr);
    asm volatile("cp.async.ca.shared.global [%0], [%1], 4;" :: "r"(sa), "l"(gptr));
}
#define CP_COMMIT asm volatile("cp.async.commit_group;")
#define CP_WAIT0  asm volatile("cp.async.wait_group 0;")

// Decentralized barrier (R4-proven): arrive = release own flag after
// syncthreads; wait = warp0 polls all 128 flags (one v4 per lane), acquire
// fence, then block-wide release via syncthreads.
__device__ __forceinline__ void barrier_arrive(int cta, unsigned e) {
    __syncthreads();   // all block work (global stores) issued before release
    if (threadIdx.x == 0) {
        unsigned* f = reinterpret_cast<unsigned*>(g_flags4) + cta;
        asm volatile("st.release.gpu.u32 [%0], %1;" :: "l"(f), "r"(e) : "memory");
    }
}
__device__ __forceinline__ void barrier_wait(unsigned e) {
    if (threadIdx.x < 32) {
        const uint4* fp = &g_flags4[threadIdx.x];
        bool ok;
        do {
            uint4 v;
            asm volatile("ld.relaxed.gpu.v4.u32 {%0,%1,%2,%3}, [%4];"
                         : "=r"(v.x), "=r"(v.y), "=r"(v.z), "=r"(v.w)
                         : "l"(fp) : "memory");
            ok = (v.x >= e) && (v.y >= e) && (v.z >= e) && (v.w >= e);
        } while (!__all_sync(0xffffffffu, ok));
        asm volatile("fence.acq_rel.gpu;" ::: "memory");
    }
    __syncthreads();
}

// Accumulate one 32-k segment with SMEM input (x): NC cols, stride WSTR.
template<int NC, int WSTR>
__device__ __forceinline__ void accum_part(const float* __restrict__ sm,
                                           unsigned long long* acc,
                                           int in_base, int w_base) {
    const float* inb = sm + in_base;
    const float* wb  = sm + w_base;
    #pragma unroll
    for (int kb = 0; kb < 8; ++kb) {
        ulonglong2 xv = *reinterpret_cast<const ulonglong2*>(inb + kb * 4);
        #pragma unroll
        for (int c = 0; c < NC; ++c) {
            ulonglong2 wv = *reinterpret_cast<const ulonglong2*>(wb + c * WSTR + kb * 4);
            fma2(acc[c], xv.x, wv.x);
            fma2(acc[c], xv.y, wv.y);
        }
    }
}

// Accumulate one 32-k segment with REGISTER input (s/h slices).
template<int NC, int WSTR>
__device__ __forceinline__ void accum_reg(const float* __restrict__ sm,
                                          unsigned long long* acc,
                                          const ulonglong2* __restrict__ xr,
                                          int w_base) {
    const float* wb = sm + w_base;
    #pragma unroll
    for (int kb = 0; kb < 8; ++kb) {
        #pragma unroll
        for (int c = 0; c < NC; ++c) {
            ulonglong2 wv = *reinterpret_cast<const ulonglong2*>(wb + c * WSTR + kb * 4);
            fma2(acc[c], xr[kb].x, wv.x);
            fma2(acc[c], xr[kb].y, wv.y);
        }
    }
}

__global__ void __launch_bounds__(TPB, 1) bislstm_kernel(
    const float* __restrict__ inputs, const float* __restrict__ mask,
    const float* __restrict__ Wx,   const float* __restrict__ Wh,
    const float* __restrict__ Ws,   const float* __restrict__ bz,
    const float* __restrict__ Wrx,  const float* __restrict__ Wrh,
    const float* __restrict__ br,
    const float* __restrict__ Wx_r, const float* __restrict__ Wh_r,
    const float* __restrict__ Ws_r, const float* __restrict__ bz_r,
    const float* __restrict__ Wrx_r,const float* __restrict__ Wrh_r,
    const float* __restrict__ br_r,
    const int* __restrict__ idx_ptr, float* __restrict__ out)
{
    extern __shared__ float sm[];
    const int tid  = threadIdx.x;
    const int warp = tid >> 5;
    const int lane = tid & 31;
    const int cta  = blockIdx.x;
    const int dir  = cta >> 6;           // 0 = fwd, 1 = rev
    const int cid  = cta & 63;
    const int jbase = cid * 4;           // this CTA's 4 hidden units
    const int idxv = *idx_ptr;
    const int w32 = warp * 32;           // warp's k-offset inside each 256-segment

    const float* pWx  = dir ? Wx_r  : Wx;
    const float* pWh  = dir ? Wh_r  : Wh;
    const float* pWs  = dir ? Ws_r  : Ws;
    const float* pB   = dir ? bz_r  : bz;
    const float* pWrx = dir ? Wrx_r : Wrx;
    const float* pWrh = dir ? Wrh_r : Wrh;
    const float* pBr  = dir ? br_r  : br;

    // ---- Load weight slices into SMEM (once) ----
    for (int i = tid; i < 16 * 768; i += TPB) {
        int k = i >> 4, c = i & 15;
        int gate = c >> 2, jj = c & 3;
        int gcol = gate * Hc + jbase + jj;
        float v;
        if (k < 256)      v = pWx[(size_t)k * (4 * Hc) + gcol];
        else if (k < 512) v = pWh[(size_t)(k - 256) * (4 * Hc) + gcol];
        else              v = pWs[(size_t)(k - 512) * (4 * Hc) + gcol];
        sm[OFF_WA + c * 772 + k] = v;
    }
    for (int i = tid; i < 8 * 512; i += TPB) {
        int k = i >> 3, c = i & 7;
        int kk = c >> 2, jj = c & 3;
        int j = jbase + jj;
        float v;
        if (k < 256) v = pWrx[(size_t)kk * Ec * Hc + (size_t)k * Hc + j];
        else         v = pWrh[(size_t)kk * Hc * Hc + (size_t)(k - 256) * Hc + j];
        sm[OFF_WB + c * 516 + k] = v;
    }
    if (tid < 16) {
        int gate = tid >> 2, jj = tid & 3;
        sm[OFF_BA + tid] = pB[gate * Hc + jbase + jj];
    }
    if (tid < 8) {
        int kk = tid >> 2, jj = tid & 3;
        sm[OFF_BB + tid] = pBr[kk * Hc + jbase + jj];
    }
    if (tid < 128) { sm[OFF_CLOC + tid] = 0.0f; sm[OFF_HTMP + tid] = 0.0f; }
    sm[OFF_SLOC + tid] = 0.0f;
    // prefetch x_0 and mask_0
    {
        const int t0 = dir ? (Sc - 1) : 0;
        for (int i = tid; i < 2048; i += TPB) {
            int b = i >> 6, k4 = i & 63;
            cp16(&sm[OFF_SIN + b * 772 + k4 * 4],
                 inputs + ((size_t)b * Sc + t0) * Ec + k4 * 4);
        }
        if (tid < 32) cp4(&sm[OFF_MASK + tid], mask + (size_t)tid * Sc + t0);
        CP_COMMIT;
    }

    unsigned e = 0;
    // acc2: z partials. Carries h-part across BAR2 (zero at step 0 since h=0).
    unsigned long long acc2[16];
    #pragma unroll
    for (int c = 0; c < 16; ++c) acc2[c] = 0ULL;
    unsigned long long accB[8];
    ulonglong2 hreg[8];

    // Per-lane global slice pointers: lane handles batch b=lane, k-slice w32.
    const float* ssrc = g_s + (size_t)(dir * 2 + idxv) * (Bc * Hc) + lane * 256 + w32;
    const float* hsrc = g_h + (size_t)dir * (Bc * Hc) + lane * 256 + w32;

    for (int n = 0; n < Sc; ++n) {
        const int t = dir ? (Sc - 1 - n) : n;

        // ===== A1: issue s reg-loads (L2), wait x, compute z x-part under them =====
        ulonglong2 sreg[8];
        #pragma unroll
        for (int j = 0; j < 8; ++j)
            sreg[j] = __ldcg(reinterpret_cast<const ulonglong2*>(ssrc + j * 4));
        CP_WAIT0;          // own x/mask copies done
        __syncthreads();   // everyone's x copies visible
        accum_part<16, 772>(sm, acc2, OFF_SIN + lane * 772 + w32, OFF_WA + w32);

        // ===== A2: z s-part (registers) + partials =====
        accum_reg<16, 772>(sm, acc2, sreg, OFF_WA + 512 + w32);
        #pragma unroll
        for (int c = 0; c < 16; ++c)
            sm[OFF_PRED + warp * 520 + c * 32 + lane] = pair_sum(acc2[c]);
        __syncthreads();

        // ===== A3: fused reduce + gates + mask blend =====
        if (tid < 128) {
            const int jj = tid >> 5, b = tid & 31;
            float zi = sm[OFF_BA + jj];
            float zf = sm[OFF_BA + 4 + jj];
            float zg = sm[OFF_BA + 8 + jj];
            float zo = sm[OFF_BA + 12 + jj];
            #pragma unroll
            for (int w = 0; w < 8; ++w) {
                const float* p = &sm[OFF_PRED + w * 520 + b];
                zi += p[(jj     ) * 32];
                zf += p[(jj +  4) * 32];
                zg += p[(jj +  8) * 32];
                zo += p[(jj + 12) * 32];
            }
            const float cold = sm[OFF_CLOC + tid];
            const float hold = sm[OFF_HTMP + tid];   // previous step's local h
            const float m    = sm[OFF_MASK + b];
            const float cn = sigf(zf) * cold + sigf(zi) * tanhf_fast(zg);
            const float hn = sigf(zo) * tanhf_fast(cn);
            const float h = m * hn + (1.0f - m) * hold;
            const float c = m * cn + (1.0f - m) * cold;
            sm[OFF_CLOC + tid] = c;
            sm[OFF_HTMP + tid] = h;
        }
        __syncthreads();

        // ===== A4: publish h + h/c outputs =====
        if (tid < 32) {
            const int b = tid;
            float4 hv = make_float4(sm[OFF_HTMP + b],      sm[OFF_HTMP + 32 + b],
                                    sm[OFF_HTMP + 64 + b], sm[OFF_HTMP + 96 + b]);
            float4 cv = make_float4(sm[OFF_CLOC + b],      sm[OFF_CLOC + 32 + b],
                                    sm[OFF_CLOC + 64 + b], sm[OFF_CLOC + 96 + b]);
            float* hp = g_h + (size_t)dir * (Bc * Hc) + b * 256 + jbase;
            *reinterpret_cast<float4*>(hp) = hv;
            size_t ob = (size_t)t * (Bc * 512) + (size_t)b * 512 + dir * 256 + jbase;
            *reinterpret_cast<float4*>(out + ob) = hv;
            *reinterpret_cast<float4*>(out + OUT_C + ob) = cv;
        }
        barrier_arrive(cta, ++e);

        // ----- BAR1 shadow: r x-part (x_n still resident in SIN) -----
        #pragma unroll
        for (int c = 0; c < 8; ++c) accB[c] = 0ULL;
        accum_part<8, 516>(sm, accB, OFF_SIN + lane * 772 + w32, OFF_WB + w32);
        barrier_wait(e);

        // ===== B1: h reg-loads (L2) feeding r h-part directly =====
        #pragma unroll
        for (int j = 0; j < 8; ++j)
            hreg[j] = __ldcg(reinterpret_cast<const ulonglong2*>(hsrc + j * 4));
        accum_reg<8, 516>(sm, accB, hreg, OFF_WB + 256 + w32);
        #pragma unroll
        for (int c = 0; c < 8; ++c)
            sm[OFF_PRED + warp * 520 + c * 32 + lane] = pair_sum(accB[c]);
        __syncthreads();

        // ===== B2: fused reduce + s update (256 threads) =====
        {
            const int o = tid;
            const int c = o >> 5, b = o & 31;
            const int jj = c & 3;
            float z = sm[OFF_BB + c];
            #pragma unroll
            for (int w = 0; w < 8; ++w) z += sm[OFF_PRED + w * 520 + o];
            const float r    = sigf(z);
            const float sold = sm[OFF_SLOC + o];
            const float cc   = sm[OFF_CLOC + jj * 32 + b];
            const float m    = sm[OFF_MASK + b];
            const float sn   = r * sold + (1.0f - r) * cc;
            sm[OFF_SLOC + o] = m * sn + (1.0f - m) * sold;
        }
        __syncthreads();

        // ===== B3: publish s + s outputs; prefetch x_{n+1}/mask =====
        if (tid < 64) {
            const int kk = tid >> 5, b = tid & 31;
            const int base = (kk * 4) * 32 + b;
            float4 sv = make_float4(sm[OFF_SLOC + base],      sm[OFF_SLOC + base + 32],
                                    sm[OFF_SLOC + base + 64], sm[OFF_SLOC + base + 96]);
            *reinterpret_cast<float4*>(
                g_s + (size_t)(dir * 2 + kk) * (Bc * Hc) + b * 256 + jbase) = sv;
            size_t ob = (size_t)kk * ((size_t)Sc * Bc * 512)
                      + (size_t)t * (Bc * 512) + (size_t)b * 512 + dir * 256 + jbase;
            *reinterpret_cast<float4*>(out + OUT_S + ob) = sv;
        }
        if (n + 1 < Sc) {
            const int tn = dir ? (Sc - 2 - n) : (n + 1);
            for (int i = tid; i < 2048; i += TPB) {
                int b = i >> 6, k4 = i & 63;
                cp16(&sm[OFF_SIN + b * 772 + k4 * 4],
                     inputs + ((size_t)b * Sc + tn) * Ec + k4 * 4);
            }
            if (tid < 32) cp4(&sm[OFF_MASK + tid], mask + (size_t)tid * Sc + tn);
            CP_COMMIT;
        }
        barrier_arrive(cta, ++e);

        // ----- BAR2 shadow: z h-part for step n+1 (from hreg, no loads) -----
        #pragma unroll
        for (int c = 0; c < 16; ++c) acc2[c] = 0ULL;
        accum_reg<16, 772>(sm, acc2, hreg, OFF_WA + 256 + w32);
        barrier_wait(e);
    }
}

extern "C" void kernel_launch(void* const* d_in, const int* in_sizes, int n_in,
                              void* d_out, int out_size) {
    (void)in_sizes; (void)n_in; (void)out_size;
    cudaFuncSetAttribute(bislstm_kernel,
                         cudaFuncAttributeMaxDynamicSharedMemorySize, SMEM_BYTES);
    init_kernel<<<64, 256>>>();
    bislstm_kernel<<<NCTA, TPB, SMEM_BYTES>>>(
        (const float*)d_in[0],  (const float*)d_in[1],
        (const float*)d_in[2],  (const float*)d_in[3],
        (const float*)d_in[4],  (const float*)d_in[5],
        (const float*)d_in[6],  (const float*)d_in[7],
        (const float*)d_in[8],
        (const float*)d_in[9],  (const float*)d_in[10],
        (const float*)d_in[11], (const float*)d_in[12],
        (const float*)d_in[13], (const float*)d_in[14],
        (const float*)d_in[15],
        (const int*)d_in[16],   (float*)d_out);
}

// round 10
// speedup vs baseline: 2.1297x; 1.0090x over previous
#include <cuda_runtime.h>
#include <math.h>

// Problem constants
#define Bc 32
#define Sc 1024
#define Ec 256
#define Hc 256
#define NCTA 128      // 64 CTAs per direction, 4 hidden units each
#define TPB 256       // 8 warps
#define NPAR 8        // parity depth of the h/s exchange buffers

// Output section offsets (floats)
#define OUT_C 16777216UL          // S*B*2H
#define OUT_S 33554432UL          // 2 * S*B*2H

// SMEM layout (float offsets)
#define OFF_WA   0        // [16 cols][772]   z-projection weights (x|h|s stacked on k)
#define OFF_WB   12352    // [8 cols][516]    r-projection weights (x|h stacked on k)
#define OFF_BA   16480    // [16]
#define OFF_BB   16496    // [16]
#define OFF_SIN  16512    // [32 b][772]      x staging (cols 0:256 used)
#define OFF_PRED 41216    // [8 warps][520]   k-split partials
#define OFF_CLOC 45376    // [4 jj][32 b]     cell state (CTA-local, persistent)
#define OFF_SLOC 45504    // [8 c][32 b]      shared state (CTA-local, persistent)
#define OFF_HTMP 45760    // [4 jj][32 b]     h state (CTA-local, persistent)
#define OFF_MASKW 45888   // [8 warps][32]    per-warp mask copies
#define SMEM_FLOATS 46144
#define SMEM_BYTES (SMEM_FLOATS * 4)

// Exchange buffers, NPAR-deep by step parity. [par][dir][b][j]
__device__ float g_h[NPAR * 2 * Bc * Hc];
__device__ float g_s[NPAR * 2 * Bc * Hc];     // share idx only
// One monotone epoch flag per CTA, padded to 32B.
__device__ unsigned g_flags[NCTA * 8];

__global__ void init_kernel() {
    int tid = blockIdx.x * blockDim.x + threadIdx.x;
    int stride = gridDim.x * blockDim.x;
    for (int i = tid; i < NPAR * 2 * Bc * Hc; i += stride) { g_h[i] = 0.0f; g_s[i] = 0.0f; }
    for (int i = tid; i < NCTA * 8; i += stride) g_flags[i] = 0u;
}

__device__ __forceinline__ float sigf(float x) {
    return __fdividef(1.0f, 1.0f + __expf(-x));
}
__device__ __forceinline__ float tanhf_fast(float x) {
    return 1.0f - __fdividef(2.0f, __expf(2.0f * x) + 1.0f);
}

// Packed dual-fp32 FMA (sm_103a).
__device__ __forceinline__ void fma2(unsigned long long& d,
                                     const unsigned long long a,
                                     const unsigned long long b) {
    asm("fma.rn.f32x2 %0, %1, %2, %0;" : "+l"(d) : "l"(a), "l"(b));
}
__device__ __forceinline__ float pair_sum(unsigned long long v) {
    float lo = __uint_as_float((unsigned int)(v & 0xffffffffULL));
    float hi = __uint_as_float((unsigned int)(v >> 32));
    return lo + hi;
}

// cp.async helpers
__device__ __forceinline__ void cp16(const float* smem_ptr, const float* gptr) {
    unsigned sa = (unsigned)__cvta_generic_to_shared(smem_ptr);
    asm volatile("cp.async.cg.shared.global [%0], [%1], 16;" :: "r"(sa), "l"(gptr));
}
__device__ __forceinline__ void cp4(const float* smem_ptr, const float* gptr) {
    unsigned sa = (unsigned)__cvta_generic_to_shared(smem_ptr);
    asm volatile("cp.async.ca.shared.global [%0], [%1], 4;" :: "r"(sa), "l"(gptr));
}
#define CP_COMMIT asm volatile("cp.async.commit_group;")
#define CP_WAIT0  asm volatile("cp.async.wait_group 0;")

// Warp-local producer wait: warp w consumes units w*32..w*32+31 produced by
// same-dir CTAs cid = w*8..w*8+7. All lanes poll (4x duplicated), acquire loads.
__device__ __forceinline__ void wait_producers(int dir, int warp, int lane, unsigned e) {
    const unsigned* fp = &g_flags[(unsigned)(dir * 64 + warp * 8 + (lane & 7)) * 8];
    unsigned v;
    do {
        asm volatile("ld.acquire.gpu.u32 %0, [%1];" : "=r"(v) : "l"(fp) : "memory");
    } while (!__all_sync(0xffffffffu, v >= e));
}

__device__ __forceinline__ void flag_release(int cta, unsigned e) {
    unsigned* f = &g_flags[(unsigned)cta * 8];
    asm volatile("st.release.gpu.u32 [%0], %1;" :: "l"(f), "r"(e) : "memory");
}

// Accumulate one 32-k segment with SMEM input (x): NC cols, stride WSTR.
template<int NC, int WSTR>
__device__ __forceinline__ void accum_part(const float* __restrict__ sm,
                                           unsigned long long* acc,
                                           int in_base, int w_base) {
    const float* inb = sm + in_base;
    const float* wb  = sm + w_base;
    #pragma unroll
    for (int kb = 0; kb < 8; ++kb) {
        ulonglong2 xv = *reinterpret_cast<const ulonglong2*>(inb + kb * 4);
        #pragma unroll
        for (int c = 0; c < NC; ++c) {
            ulonglong2 wv = *reinterpret_cast<const ulonglong2*>(wb + c * WSTR + kb * 4);
            fma2(acc[c], xv.x, wv.x);
            fma2(acc[c], xv.y, wv.y);
        }
    }
}

// Accumulate one 32-k segment with REGISTER input (s/h slices).
template<int NC, int WSTR>
__device__ __forceinline__ void accum_reg(const float* __restrict__ sm,
                                          unsigned long long* acc,
                                          const ulonglong2* __restrict__ xr,
                                          int w_base) {
    const float* wb = sm + w_base;
    #pragma unroll
    for (int kb = 0; kb < 8; ++kb) {
        #pragma unroll
        for (int c = 0; c < NC; ++c) {
            ulonglong2 wv = *reinterpret_cast<const ulonglong2*>(wb + c * WSTR + kb * 4);
            fma2(acc[c], xr[kb].x, wv.x);
            fma2(acc[c], xr[kb].y, wv.y);
        }
    }
}

__global__ void __launch_bounds__(TPB, 1) bislstm_kernel(
    const float* __restrict__ inputs, const float* __restrict__ mask,
    const float* __restrict__ Wx,   const float* __restrict__ Wh,
    const float* __restrict__ Ws,   const float* __restrict__ bz,
    const float* __restrict__ Wrx,  const float* __restrict__ Wrh,
    const float* __restrict__ br,
    const float* __restrict__ Wx_r, const float* __restrict__ Wh_r,
    const float* __restrict__ Ws_r, const float* __restrict__ bz_r,
    const float* __restrict__ Wrx_r,const float* __restrict__ Wrh_r,
    const float* __restrict__ br_r,
    const int* __restrict__ idx_ptr, float* __restrict__ out)
{
    extern __shared__ float sm[];
    const int tid  = threadIdx.x;
    const int warp = tid >> 5;
    const int lane = tid & 31;
    const int cta  = blockIdx.x;
    const int dir  = cta >> 6;           // 0 = fwd, 1 = rev
    const int cid  = cta & 63;
    const int jbase = cid * 4;           // this CTA's 4 hidden units
    const int idxv = *idx_ptr;
    const int w32 = warp * 32;           // warp's k-offset inside each 256-segment

    const float* pWx  = dir ? Wx_r  : Wx;
    const float* pWh  = dir ? Wh_r  : Wh;
    const float* pWs  = dir ? Ws_r  : Ws;
    const float* pB   = dir ? bz_r  : bz;
    const float* pWrx = dir ? Wrx_r : Wrx;
    const float* pWrh = dir ? Wrh_r : Wrh;
    const float* pBr  = dir ? br_r  : br;

    // ---- Load weight slices into SMEM (once) ----
    for (int i = tid; i < 16 * 768; i += TPB) {
        int k = i >> 4, c = i & 15;
        int gate = c >> 2, jj = c & 3;
        int gcol = gate * Hc + jbase + jj;
        float v;
        if (k < 256)      v = pWx[(size_t)k * (4 * Hc) + gcol];
        else if (k < 512) v = pWh[(size_t)(k - 256) * (4 * Hc) + gcol];
        else              v = pWs[(size_t)(k - 512) * (4 * Hc) + gcol];
        sm[OFF_WA + c * 772 + k] = v;
    }
    for (int i = tid; i < 8 * 512; i += TPB) {
        int k = i >> 3, c = i & 7;
        int kk = c >> 2, jj = c & 3;
        int j = jbase + jj;
        float v;
        if (k < 256) v = pWrx[(size_t)kk * Ec * Hc + (size_t)k * Hc + j];
        else         v = pWrh[(size_t)kk * Hc * Hc + (size_t)(k - 256) * Hc + j];
        sm[OFF_WB + c * 516 + k] = v;
    }
    if (tid < 16) {
        int gate = tid >> 2, jj = tid & 3;
        sm[OFF_BA + tid] = pB[gate * Hc + jbase + jj];
    }
    if (tid < 8) {
        int kk = tid >> 2, jj = tid & 3;
        sm[OFF_BB + tid] = pBr[kk * Hc + jbase + jj];
    }
    if (tid < 128) { sm[OFF_CLOC + tid] = 0.0f; sm[OFF_HTMP + tid] = 0.0f; }
    sm[OFF_SLOC + tid] = 0.0f;

    // prefetch x_0 / mask_0: per-warp self-sufficient mapping —
    // lane l copies exactly the chunks it will read: row b=l, cols w32..w32+31.
    {
        const int t0 = dir ? (Sc - 1) : 0;
        const float* xrow = inputs + ((size_t)lane * Sc + t0) * Ec + w32;
        #pragma unroll
        for (int j = 0; j < 8; ++j)
            cp16(&sm[OFF_SIN + lane * 772 + w32 + j * 4], xrow + j * 4);
        cp4(&sm[OFF_MASKW + warp * 32 + lane], mask + (size_t)lane * Sc + t0);
        CP_COMMIT;
    }
    __syncthreads();

    // acc2: z partials. Carries h-part across step boundary (zero at step 0).
    unsigned long long acc2[16];
    #pragma unroll
    for (int c = 0; c < 16; ++c) acc2[c] = 0ULL;
    unsigned long long accB[8];
    ulonglong2 hreg[8];
    unsigned cached_min = 0;   // warp0's cached min of same-dir flags

    for (int n = 0; n < Sc; ++n) {
        const int t = dir ? (Sc - 1 - n) : n;
        const int wpar = n & (NPAR - 1);            // write parity (h_n, s_n)
        const int rpar = (n + NPAR - 1) & (NPAR - 1); // read parity (s_{n-1})

        // ===== A: wait own x; wait s producers; z = x+s+h parts =====
        CP_WAIT0;                      // own lanes' x/mask copies complete
        wait_producers(dir, warp, lane, 2u * n);     // s_{n-1} visible (e=0 trivial)
        {
            const float* ssrc = g_s + ((size_t)rpar * 2 + dir) * (Bc * Hc) + lane * 256 + w32;
            ulonglong2 sreg[8];
            #pragma unroll
            for (int j = 0; j < 8; ++j)
                sreg[j] = __ldcg(reinterpret_cast<const ulonglong2*>(ssrc + j * 4));
            accum_part<16, 772>(sm, acc2, OFF_SIN + lane * 772 + w32, OFF_WA + w32);
            accum_reg<16, 772>(sm, acc2, sreg, OFF_WA + 512 + w32);
        }
        #pragma unroll
        for (int c = 0; c < 16; ++c)
            sm[OFF_PRED + warp * 520 + c * 32 + lane] = pair_sum(acc2[c]);
        __syncthreads();

        // ===== A2: fused reduce + gates + mask blend =====
        if (tid < 128) {
            const int jj = tid >> 5, b = tid & 31;
            float zi = sm[OFF_BA + jj];
            float zf = sm[OFF_BA + 4 + jj];
            float zg = sm[OFF_BA + 8 + jj];
            float zo = sm[OFF_BA + 12 + jj];
            #pragma unroll
            for (int w = 0; w < 8; ++w) {
                const float* p = &sm[OFF_PRED + w * 520 + b];
                zi += p[(jj     ) * 32];
                zf += p[(jj +  4) * 32];
                zg += p[(jj +  8) * 32];
                zo += p[(jj + 12) * 32];
            }
            const float cold = sm[OFF_CLOC + tid];
            const float hold = sm[OFF_HTMP + tid];
            const float m    = sm[OFF_MASKW + (tid >> 5) * 32 + b];
            const float cn = sigf(zf) * cold + sigf(zi) * tanhf_fast(zg);
            const float hn = sigf(zo) * tanhf_fast(cn);
            const float h = m * hn + (1.0f - m) * hold;
            const float c = m * cn + (1.0f - m) * cold;
            sm[OFF_CLOC + tid] = c;
            sm[OFF_HTMP + tid] = h;
        }
        __syncthreads();

        // ===== A3: warp0: anti-dependency bound, publish h + h/c outputs, flag =====
        if (tid < 32) {
            // Writers of parity wpar overwrite h_{n-NPAR}/s_{n-NPAR}; all same-dir
            // CTAs must have finished reading them: min flag >= 2n-13 (NPAR=8).
            int need = 2 * n - (2 * NPAR - 3);
            if (need > 0) {
                while ((int)cached_min < need) {
                    unsigned m = 0xffffffffu;
                    #pragma unroll
                    for (int q = 0; q < 2; ++q) {
                        unsigned vv;
                        const unsigned* fp = &g_flags[(unsigned)(dir * 64 + lane * 2 + q) * 8];
                        asm volatile("ld.relaxed.gpu.u32 %0, [%1];" : "=r"(vv) : "l"(fp) : "memory");
                        if (vv < m) m = vv;
                    }
                    cached_min = __reduce_min_sync(0xffffffffu, m);
                }
            }
            const int b = tid;
            float4 hv = make_float4(sm[OFF_HTMP + b],      sm[OFF_HTMP + 32 + b],
                                    sm[OFF_HTMP + 64 + b], sm[OFF_HTMP + 96 + b]);
            float4 cv = make_float4(sm[OFF_CLOC + b],      sm[OFF_CLOC + 32 + b],
                                    sm[OFF_CLOC + 64 + b], sm[OFF_CLOC + 96 + b]);
            float* hp = g_h + ((size_t)wpar * 2 + dir) * (Bc * Hc) + b * 256 + jbase;
            *reinterpret_cast<float4*>(hp) = hv;
            size_t ob = (size_t)t * (Bc * 512) + (size_t)b * 512 + dir * 256 + jbase;
            *reinterpret_cast<float4*>(out + ob) = hv;
            *reinterpret_cast<float4*>(out + OUT_C + ob) = cv;
            __syncwarp();
            if (lane == 0) flag_release(cta, 2u * n + 1u);
        }

        // ===== B0: r x-part (x_n still resident, own-lane rows) =====
        #pragma unroll
        for (int c = 0; c < 8; ++c) accB[c] = 0ULL;
        accum_part<8, 516>(sm, accB, OFF_SIN + lane * 772 + w32, OFF_WB + w32);

        // ===== B1: wait h producers; r h-part from registers =====
        wait_producers(dir, warp, lane, 2u * n + 1u);
        {
            const float* hsrc = g_h + ((size_t)wpar * 2 + dir) * (Bc * Hc) + lane * 256 + w32;
            #pragma unroll
            for (int j = 0; j < 8; ++j)
                hreg[j] = __ldcg(reinterpret_cast<const ulonglong2*>(hsrc + j * 4));
        }
        accum_reg<8, 516>(sm, accB, hreg, OFF_WB + 256 + w32);
        #pragma unroll
        for (int c = 0; c < 8; ++c)
            sm[OFF_PRED + warp * 520 + c * 32 + lane] = pair_sum(accB[c]);
        __syncthreads();

        // ===== B2: fused reduce + s update (256 threads) =====
        {
            const int o = tid;
            const int c = o >> 5, b = o & 31;
            const int jj = c & 3;
            float z = sm[OFF_BB + c];
            #pragma unroll
            for (int w = 0; w < 8; ++w) z += sm[OFF_PRED + w * 520 + o];
            const float r    = sigf(z);
            const float sold = sm[OFF_SLOC + o];
            const float cc   = sm[OFF_CLOC + jj * 32 + b];
            const float m    = sm[OFF_MASKW + (tid >> 5) * 32 + b];
            const float sn   = r * sold + (1.0f - r) * cc;
            sm[OFF_SLOC + o] = m * sn + (1.0f - m) * sold;
        }
        __syncthreads();

        // ===== B3: publish s[idx] + s outputs (warp0), flag; prefetch x_{n+1} =====
        if (tid < 32) {
            const int b = tid;
            const int ibase = (idxv * 4) * 32 + b;
            float4 siv = make_float4(sm[OFF_SLOC + ibase],      sm[OFF_SLOC + ibase + 32],
                                     sm[OFF_SLOC + ibase + 64], sm[OFF_SLOC + ibase + 96]);
            *reinterpret_cast<float4*>(
                g_s + ((size_t)wpar * 2 + dir) * (Bc * Hc) + b * 256 + jbase) = siv;
            #pragma unroll
            for (int kk = 0; kk < 2; ++kk) {
                const int base = (kk * 4) * 32 + b;
                float4 sv = make_float4(sm[OFF_SLOC + base],      sm[OFF_SLOC + base + 32],
                                        sm[OFF_SLOC + base + 64], sm[OFF_SLOC + base + 96]);
                size_t ob = (size_t)kk * ((size_t)Sc * Bc * 512)
                          + (size_t)t * (Bc * 512) + (size_t)b * 512 + dir * 256 + jbase;
                *reinterpret_cast<float4*>(out + OUT_S + ob) = sv;
            }
            __syncwarp();
            if (lane == 0) flag_release(cta, 2u * n + 2u);
        }
        if (n + 1 < Sc) {
            const int tn = dir ? (Sc - 2 - n) : (n + 1);
            const float* xrow = inputs + ((size_t)lane * Sc + tn) * Ec + w32;
            #pragma unroll
            for (int j = 0; j < 8; ++j)
                cp16(&sm[OFF_SIN + lane * 772 + w32 + j * 4], xrow + j * 4);
            cp4(&sm[OFF_MASKW + warp * 32 + lane], mask + (size_t)lane * Sc + tn);
        }
        CP_COMMIT;

        // ===== B4: z h-part for step n+1 (from hreg, no loads, no sync) =====
        #pragma unroll
        for (int c = 0; c < 16; ++c) acc2[c] = 0ULL;
        accum_reg<16, 772>(sm, acc2, hreg, OFF_WA + 256 + w32);
    }
}

extern "C" void kernel_launch(void* const* d_in, const int* in_sizes, int n_in,
                              void* d_out, int out_size) {
    (void)in_sizes; (void)n_in; (void)out_size;
    cudaFuncSetAttribute(bislstm_kernel,
                         cudaFuncAttributeMaxDynamicSharedMemorySize, SMEM_BYTES);
    init_kernel<<<64, 256>>>();
    bislstm_kernel<<<NCTA, TPB, SMEM_BYTES>>>(
        (const float*)d_in[0],  (const float*)d_in[1],
        (const float*)d_in[2],  (const float*)d_in[3],
        (const float*)d_in[4],  (const float*)d_in[5],
        (const float*)d_in[6],  (const float*)d_in[7],
        (const float*)d_in[8],
        (const float*)d_in[9],  (const float*)d_in[10],
        (const float*)d_in[11], (const float*)d_in[12],
        (const float*)d_in[13], (const float*)d_in[14],
        (const float*)d_in[15],
        (const int*)d_in[16],   (float*)d_out);
}